// round 3
// baseline (speedup 1.0000x reference)
#include <cuda_runtime.h>

#define N_ITEMS  262144
#define DIM      128
#define NCB      3
#define KCW      256
#define MT       64          // items per CTA
#define NTHREADS 256
#define RS       132         // smem row stride (floats), breaks bank conflicts

#define SMEM_FLOATS (KCW*RS + MT*RS + MT*RS + KCW + MT + MT*32 + MT*32 + MT)
#define SMEM_BYTES  (SMEM_FLOATS * 4)

__global__ __launch_bounds__(NTHREADS, 1)
void rvq_kernel(const float* __restrict__ x,
                const float* __restrict__ codebooks,
                float* __restrict__ out, int mode)
{
    extern __shared__ float sm[];
    float* cb   = sm;
    float* rres = cb   + KCW * RS;
    float* qacc = rres + MT * RS;
    float* cc   = qacc + MT * RS;
    float* rrs  = cc   + KCW;
    float* redv = rrs  + MT;
    int*   redi = (int*)(redv + MT * 32);
    int*   best = redi + MT * 32;

    const int t  = threadIdx.x;
    const int ig = t & 7;     // item group  (items ig + 8u)
    const int cg = t >> 3;    // cw group    (cws   cg + 32v)
    const int itemBase = blockIdx.x * MT;

    // ---- load x tile into rres (residual starts as x); qacc = 0 ----
    {
        const float4* xg = (const float4*)(x + (size_t)itemBase * DIM);
        #pragma unroll
        for (int n = 0; n < (MT * DIM / 4) / NTHREADS; n++) {   // 8
            int idx = t + NTHREADS * n;
            int row = idx >> 5;            // 32 float4 per row
            int c4  = idx & 31;
            float4 v = xg[idx];
            float* dr = &rres[row * RS + 4 * c4];
            dr[0] = v.x; dr[1] = v.y; dr[2] = v.z; dr[3] = v.w;
            float* dq = &qacc[row * RS + 4 * c4];
            dq[0] = 0.f; dq[1] = 0.f; dq[2] = 0.f; dq[3] = 0.f;
        }
    }

    for (int stage = 0; stage < NCB; stage++) {
        __syncthreads();
        // ---- load codebook[stage] into smem ----
        {
            const float4* cgm = (const float4*)(codebooks + (size_t)stage * KCW * DIM);
            #pragma unroll
            for (int n = 0; n < (KCW * DIM / 4) / NTHREADS; n++) {  // 32
                int idx = t + NTHREADS * n;
                int row = idx >> 5;
                int c4  = idx & 31;
                float4 v = cgm[idx];
                float* d = &cb[row * RS + 4 * c4];
                d[0] = v.x; d[1] = v.y; d[2] = v.z; d[3] = v.w;
            }
        }
        __syncthreads();

        // ---- cc[j] = ||c_j||^2 in double, rounded to fp32 once ----
        {
            double s = 0.0;
            const float* rowp = &cb[t * RS];
            #pragma unroll 8
            for (int k = 0; k < DIM; k++) {
                double v = (double)rowp[k];
                s += v * v;
            }
            cc[t] = (float)s;
        }
        // ---- rrs[i] = ||r_i||^2 in double, rounded to fp32 once ----
        if (t < MT) {
            double s = 0.0;
            const float* rowp = &rres[t * RS];
            #pragma unroll 8
            for (int k = 0; k < DIM; k++) {
                double v = (double)rowp[k];
                s += v * v;
            }
            rrs[t] = (float)s;
        }
        __syncthreads();

        // ---- 64x256x128 dot tile: acc[u][v] = r_i . c_j ----
        // STRICT sequential FMA chain over k ascending per output element,
        // matching canonical sgemm accumulation (cutlass SIMT / oneDNN).
        float acc[8][8];
        #pragma unroll
        for (int u = 0; u < 8; u++)
            #pragma unroll
            for (int v = 0; v < 8; v++) acc[u][v] = 0.f;

        #pragma unroll 1
        for (int k4 = 0; k4 < DIM / 4; k4++) {
            float4 rv[8], cv[8];
            #pragma unroll
            for (int u = 0; u < 8; u++)
                rv[u] = *(const float4*)&rres[(ig + 8 * u) * RS + 4 * k4];
            #pragma unroll
            for (int v = 0; v < 8; v++)
                cv[v] = *(const float4*)&cb[(cg + 32 * v) * RS + 4 * k4];
            #pragma unroll
            for (int kk = 0; kk < 4; kk++) {
                #pragma unroll
                for (int u = 0; u < 8; u++) {
                    float r = (kk == 0) ? rv[u].x : (kk == 1) ? rv[u].y
                             : (kk == 2) ? rv[u].z : rv[u].w;
                    #pragma unroll
                    for (int v = 0; v < 8; v++) {
                        float c = (kk == 0) ? cv[v].x : (kk == 1) ? cv[v].y
                                 : (kk == 2) ? cv[v].z : cv[v].w;
                        acc[u][v] = __fmaf_rn(r, c, acc[u][v]);
                    }
                }
            }
        }

        // ---- per-thread argmin of d2 = fl(fl(rr - 2*dot) + cc) ----
        #pragma unroll
        for (int u = 0; u < 8; u++) {
            int item = ig + 8 * u;
            float rrv = rrs[item];
            float bv = 3.0e38f; int bi = KCW;
            #pragma unroll
            for (int v = 0; v < 8; v++) {
                int cw = cg + 32 * v;          // ascending within thread
                float d2 = __fadd_rn(__fmaf_rn(-2.0f, acc[u][v], rrv), cc[cw]);
                if (d2 < bv) { bv = d2; bi = cw; }   // strict: keeps lowest cw on ties
            }
            redv[item * 32 + cg] = bv;
            redi[item * 32 + cg] = bi;
        }
        __syncthreads();

        // ---- reduce 32 slots per item; tie-break: smaller index ----
        if (t < MT) {
            float bv = 3.0e38f; int bi = KCW;
            #pragma unroll 4
            for (int s2 = 0; s2 < 32; s2++) {
                float v = redv[t * 32 + s2];
                int   i2 = redi[t * 32 + s2];
                if (v < bv || (v == bv && i2 < bi)) { bv = v; bi = i2; }
            }
            best[t] = bi;
            size_t gi = (size_t)(itemBase + t);
            if (mode == 0)      out[gi * 3 + stage] = (float)bi;       // concat: idx as float
            else if (mode == 2) ((int*)out)[gi * 3 + stage] = bi;      // idx only, int32
        }
        __syncthreads();

        // ---- residual -= chosen codeword; quantized += chosen codeword ----
        #pragma unroll
        for (int n = 0; n < (MT * DIM / 4) / NTHREADS; n++) {   // 8
            int e    = t + NTHREADS * n;
            int item = e >> 5;
            int c4   = e & 31;
            int bi   = best[item];
            float4 cv = *(const float4*)&cb[bi * RS + 4 * c4];
            float4 rv = *(float4*)&rres[item * RS + 4 * c4];
            rv.x = __fsub_rn(rv.x, cv.x); rv.y = __fsub_rn(rv.y, cv.y);
            rv.z = __fsub_rn(rv.z, cv.z); rv.w = __fsub_rn(rv.w, cv.w);
            *(float4*)&rres[item * RS + 4 * c4] = rv;
            float4 qv = *(float4*)&qacc[item * RS + 4 * c4];
            qv.x = __fadd_rn(qv.x, cv.x); qv.y = __fadd_rn(qv.y, cv.y);
            qv.z = __fadd_rn(qv.z, cv.z); qv.w = __fadd_rn(qv.w, cv.w);
            *(float4*)&qacc[item * RS + 4 * c4] = qv;
        }
    }
    __syncthreads();

    // ---- write quantized (accumulated in reference stage order) ----
    if (mode != 2) {
        float* outq = (mode == 0) ? (out + (size_t)N_ITEMS * 3) : out;
        float4* oq4 = (float4*)outq;
        #pragma unroll
        for (int n = 0; n < (MT * DIM / 4) / NTHREADS; n++) {   // 8
            int e    = t + NTHREADS * n;
            int item = e >> 5;
            int c4   = e & 31;
            float4 qv = *(float4*)&qacc[item * RS + 4 * c4];
            oq4[(size_t)itemBase * (DIM / 4) + e] = qv;
        }
    }
}

extern "C" void kernel_launch(void* const* d_in, const int* in_sizes, int n_in,
                              void* d_out, int out_size)
{
    const float* x   = (const float*)d_in[0];
    const float* cbk = (const float*)d_in[1];
    if (n_in >= 2 && in_sizes[0] == NCB * KCW * DIM && in_sizes[1] == N_ITEMS * DIM) {
        const float* tmp = x; x = cbk; cbk = tmp;
    }

    int mode;
    if (out_size == N_ITEMS * (3 + DIM))      mode = 0;  // [indices | quantized] concat
    else if (out_size == N_ITEMS * DIM)       mode = 1;  // quantized only
    else if (out_size == N_ITEMS * 3)         mode = 2;  // indices only, int32
    else                                       mode = (out_size > N_ITEMS * DIM) ? 0 : 1;

    cudaFuncSetAttribute(rvq_kernel, cudaFuncAttributeMaxDynamicSharedMemorySize, SMEM_BYTES);
    rvq_kernel<<<N_ITEMS / MT, NTHREADS, SMEM_BYTES>>>(x, cbk, (float*)d_out, mode);
}